// round 10
// baseline (speedup 1.0000x reference)
#include <cuda_runtime.h>
#include <cuda_fp16.h>
#include <math.h>

#define NMAX 100000
#define EMAX 1600000
#define HID 128
#define NGRAPH 64
#define SCAN_BLK 512

// ---------------- device scratch ----------------
__device__ __half g_xh[(size_t)NMAX * HID];    // fp16 copy of x
__device__ __half g_wt[HID * HID];             // fp16 W_gcn transposed
__device__ __half g_yh[(size_t)NMAX * HID];    // fp16 xt = x@W, then scaled by dinv in k_yscale
__device__ float g_dinv[NMAX];
__device__ int   g_deg[NMAX];
__device__ int   g_start[NMAX + 1];
__device__ int   g_cursor[NMAX];
__device__ int   g_csr_src[EMAX];
__device__ int   g_part[(NMAX + SCAN_BLK - 1) / SCAN_BLK];
__device__ float g_gsum[NGRAPH * HID];
__device__ float g_gcnt[NGRAPH];
__device__ float g_gatesX[NGRAPH * 4 * HID];
__device__ __half g_whh_h[4 * HID * HID];

// ---------------- fp16 conversions ----------------
__global__ void k_cvtx(const float* __restrict__ x, int total8) {
    int i = blockIdx.x * blockDim.x + threadIdx.x;
    if (i < total8) {
        float4 v0 = __ldg((const float4*)x + (size_t)i * 2);
        float4 v1 = __ldg((const float4*)x + (size_t)i * 2 + 1);
        __half2 h0 = __floats2half2_rn(v0.x, v0.y);
        __half2 h1 = __floats2half2_rn(v0.z, v0.w);
        __half2 h2 = __floats2half2_rn(v1.x, v1.y);
        __half2 h3 = __floats2half2_rn(v1.z, v1.w);
        uint4 p;
        p.x = *(unsigned*)&h0; p.y = *(unsigned*)&h1;
        p.z = *(unsigned*)&h2; p.w = *(unsigned*)&h3;
        *(uint4*)(g_xh + (size_t)i * 8) = p;
    }
}

__global__ void k_cvtw(const float* __restrict__ W, const float* __restrict__ w_hh) {
    int i = blockIdx.x * blockDim.x + threadIdx.x;
    if (i < HID * HID) {
        int n = i >> 7, k = i & 127;
        g_wt[n * HID + k] = __float2half(__ldg(&W[k * HID + n]));
    }
    if (i < 4 * HID * HID) g_whh_h[i] = __float2half(__ldg(&w_hh[i]));
}

// ---------------- init ----------------
__global__ void k_init(int N) {
    int i = blockIdx.x * blockDim.x + threadIdx.x;
    if (i < N) g_deg[i] = 0;
    if (i < NGRAPH * HID) g_gsum[i] = 0.f;
    if (i < NGRAPH) g_gcnt[i] = 0.f;
}

// ---------------- degree histogram over col ----------------
__global__ void k_deg(const int* __restrict__ ei, int E) {
    int e = blockIdx.x * blockDim.x + threadIdx.x;
    if (e < E) atomicAdd(&g_deg[__ldg(&ei[(size_t)E + e])], 1);
}

// ---------------- scan pass 1: block sums + dinv ----------------
__global__ __launch_bounds__(SCAN_BLK) void k_scan1(int N) {
    int i = blockIdx.x * SCAN_BLK + threadIdx.x;
    int v = (i < N) ? g_deg[i] : 0;
    if (i < N) g_dinv[i] = rsqrtf((float)v + 1.0f);
    int s = v;
    for (int o = 16; o > 0; o >>= 1) s += __shfl_down_sync(0xffffffffu, s, o);
    __shared__ int ws[16];
    int wid = threadIdx.x >> 5, lane = threadIdx.x & 31;
    if (lane == 0) ws[wid] = s;
    __syncthreads();
    if (threadIdx.x < 16) {
        int t = ws[threadIdx.x];
        for (int o = 8; o > 0; o >>= 1) t += __shfl_down_sync(0xffffu, t, o);
        if (threadIdx.x == 0) g_part[blockIdx.x] = t;
    }
}

// ---------------- scan pass 2+3 merged: each block sums partials [0..bid) itself ----------------
__global__ __launch_bounds__(SCAN_BLK) void k_scan23(int N, int NB) {
    int bid = blockIdx.x;
    int i = bid * SCAN_BLK + threadIdx.x;
    int v = (i < N) ? g_deg[i] : 0;
    int lane = threadIdx.x & 31, wid = threadIdx.x >> 5;
    // block-wide inclusive scan of v
    int x = v;
    for (int o = 1; o < 32; o <<= 1) {
        int t = __shfl_up_sync(0xffffffffu, x, o);
        if (lane >= o) x += t;
    }
    __shared__ int ws[16], pws[16], sbase;
    if (lane == 31) ws[wid] = x;
    // partial-sum of g_part[0..bid)
    int pv = ((int)threadIdx.x < bid) ? g_part[threadIdx.x] : 0;
    for (int o = 16; o > 0; o >>= 1) pv += __shfl_down_sync(0xffffffffu, pv, o);
    if (lane == 0) pws[wid] = pv;
    __syncthreads();
    if (wid == 0 && lane < 16) {
        int t = ws[lane];
        for (int o = 1; o < 16; o <<= 1) {
            int u = __shfl_up_sync(0xffffu, t, o);
            if (lane >= o) t += u;
        }
        ws[lane] = t;
    }
    if (wid == 1 && lane < 16) {
        int t = pws[lane];
        for (int o = 8; o > 0; o >>= 1) t += __shfl_down_sync(0xffffu, t, o);
        if (lane == 0) sbase = t;
    }
    __syncthreads();
    int base = sbase + (wid > 0 ? ws[wid - 1] : 0);
    int excl = base + (x - v);
    if (i < N) { g_start[i] = excl; g_cursor[i] = excl; }
    if (i == N - 1) g_start[N] = excl + v;
}

// ---------------- CSR fill ----------------
__global__ void k_fill(const int* __restrict__ ei, int E) {
    int e = blockIdx.x * blockDim.x + threadIdx.x;
    if (e < E) {
        int row = __ldg(&ei[e]);
        int col = __ldg(&ei[(size_t)E + e]);
        int slot = atomicAdd(&g_cursor[col], 1);
        g_csr_src[slot] = row;
    }
}

// ---------------- tensor-core GEMM: yh[n] = fp16( x[n] @ W ) ----------------
__global__ __launch_bounds__(256) void k_gemm_tc(int M) {
    __shared__ __half xs[128][72];
    __shared__ __half ws[128][72];
    int tid = threadIdx.x;
    int warp = tid >> 5, lane = tid & 31;
    int wm = (warp & 3) * 32;
    int wn = (warp >> 2) * 64;
    int g = lane >> 2, tig = lane & 3;
    int m0 = blockIdx.x * 128;

    float acc[2][8][4];
#pragma unroll
    for (int mt = 0; mt < 2; mt++)
#pragma unroll
        for (int nt = 0; nt < 8; nt++)
#pragma unroll
            for (int q = 0; q < 4; q++) acc[mt][nt][q] = 0.f;

    for (int kc = 0; kc < 2; kc++) {
#pragma unroll
        for (int i = 0; i < 4; i++) {
            int idx = i * 256 + tid;
            int r = idx >> 3, q = idx & 7;
            int grow = m0 + r;
            uint4 v = make_uint4(0u, 0u, 0u, 0u);
            if (grow < M)
                v = *(const uint4*)(g_xh + (size_t)grow * HID + kc * 64 + q * 8);
            *(uint4*)(&xs[r][q * 8]) = v;
            uint4 w = *(const uint4*)(g_wt + r * HID + kc * 64 + q * 8);
            *(uint4*)(&ws[r][q * 8]) = w;
        }
        __syncthreads();
#pragma unroll
        for (int ks = 0; ks < 4; ks++) {
            int k0 = ks * 16;
            unsigned a[2][4];
#pragma unroll
            for (int mt = 0; mt < 2; mt++) {
                int row = wm + mt * 16 + g;
                a[mt][0] = *(const unsigned*)(&xs[row][k0 + tig * 2]);
                a[mt][1] = *(const unsigned*)(&xs[row + 8][k0 + tig * 2]);
                a[mt][2] = *(const unsigned*)(&xs[row][k0 + tig * 2 + 8]);
                a[mt][3] = *(const unsigned*)(&xs[row + 8][k0 + tig * 2 + 8]);
            }
#pragma unroll
            for (int nt = 0; nt < 8; nt++) {
                int n = wn + nt * 8 + g;
                unsigned b0 = *(const unsigned*)(&ws[n][k0 + tig * 2]);
                unsigned b1 = *(const unsigned*)(&ws[n][k0 + tig * 2 + 8]);
#pragma unroll
                for (int mt = 0; mt < 2; mt++) {
                    float* c = acc[mt][nt];
                    asm volatile(
                        "mma.sync.aligned.m16n8k16.row.col.f32.f16.f16.f32 "
                        "{%0,%1,%2,%3}, {%4,%5,%6,%7}, {%8,%9}, {%0,%1,%2,%3};"
                        : "+f"(c[0]), "+f"(c[1]), "+f"(c[2]), "+f"(c[3])
                        : "r"(a[mt][0]), "r"(a[mt][1]), "r"(a[mt][2]), "r"(a[mt][3]),
                          "r"(b0), "r"(b1));
                }
            }
        }
        __syncthreads();
    }

#pragma unroll
    for (int mt = 0; mt < 2; mt++) {
        int row = m0 + wm + mt * 16 + g;
#pragma unroll
        for (int nt = 0; nt < 8; nt++) {
            int col = wn + nt * 8 + tig * 2;
            float* c = acc[mt][nt];
            if (row < M) {
                __half2 h = __floats2half2_rn(c[0], c[1]);
                *(__half2*)(g_yh + (size_t)row * HID + col) = h;
            }
            if (row + 8 < M) {
                __half2 h = __floats2half2_rn(c[2], c[3]);
                *(__half2*)(g_yh + (size_t)(row + 8) * HID + col) = h;
            }
        }
    }
}

// ---------------- yscale: g_yh[n] *= dinv[n]  (runs on s2 after gemm + scan1) ----------------
__global__ void k_yscale(int total16) {   // total16 = N*16, each thread: 8 halves
    int i = blockIdx.x * blockDim.x + threadIdx.x;
    if (i < total16) {
        int n = i >> 4;
        uint4 v = *(const uint4*)(g_yh + (size_t)i * 8);
        __half2 dh = __float2half2_rn(g_dinv[n]);
        __half2* p = (__half2*)&v;
        p[0] = __hmul2(p[0], dh);
        p[1] = __hmul2(p[1], dh);
        p[2] = __hmul2(p[2], dh);
        p[3] = __hmul2(p[3], dh);
        *(uint4*)(g_yh + (size_t)i * 8) = v;
    }
}

// ---------------- agg v3: half-warp per edge, fp16 accumulate ----------------
__device__ __forceinline__ __half2 h2_xor16(__half2 v) {
    unsigned u = *(unsigned*)&v;
    u = __shfl_xor_sync(0xffffffffu, u, 16);
    return *(__half2*)&u;
}

__global__ __launch_bounds__(256) void k_agg(const int* __restrict__ batch,
                                             const float* __restrict__ b_gcn, int N) {
    int lane = threadIdx.x & 31, wid = threadIdx.x >> 5;
    int hl = lane & 15;       // dim group: dims [hl*8, hl*8+8)
    int half = lane >> 4;     // which edge of a pair
    int s0 = blockIdx.x * 32;
    int e0 = min(s0 + 32, N);
    int n0 = s0 + wid;
    if (n0 >= e0) return;

    float4 bbA = __ldg((const float4*)(b_gcn + hl * 8));
    float4 bbB = __ldg((const float4*)(b_gcn + hl * 8 + 4));
    int curg = __ldg(&batch[n0]);
    float4 runA = make_float4(0.f, 0.f, 0.f, 0.f);
    float4 runB = make_float4(0.f, 0.f, 0.f, 0.f);
    float crun = 0.f;

    for (int n = n0; n < e0; n += 8) {
        int gg = __ldg(&batch[n]);
        if (gg != curg) {
            if (lane < 16) {
                float* dA = g_gsum + curg * HID + hl * 8;
                asm volatile("red.global.add.v4.f32 [%0], {%1,%2,%3,%4};"
                             :: "l"(dA), "f"(runA.x), "f"(runA.y), "f"(runA.z), "f"(runA.w) : "memory");
                asm volatile("red.global.add.v4.f32 [%0], {%1,%2,%3,%4};"
                             :: "l"(dA + 4), "f"(runB.x), "f"(runB.y), "f"(runB.z), "f"(runB.w) : "memory");
            }
            if (lane == 0) atomicAdd(&g_gcnt[curg], crun);
            runA = make_float4(0.f, 0.f, 0.f, 0.f);
            runB = make_float4(0.f, 0.f, 0.f, 0.f);
            crun = 0.f;
            curg = gg;
        }
        int st = __ldg(&g_start[n]);
        int en = __ldg(&g_start[n + 1]);
        float dvn = __ldg(&g_dinv[n]);
        // self row seeds half 0; half 1 starts at zero
        __half2 a0, a1, a2, a3;
        {
            uint4 r = __ldg((const uint4*)(g_yh + (size_t)n * HID + hl * 8));
            __half2 z = __float2half2_rn(0.f);
            a0 = half ? z : *(__half2*)&r.x;
            a1 = half ? z : *(__half2*)&r.y;
            a2 = half ? z : *(__half2*)&r.z;
            a3 = half ? z : *(__half2*)&r.w;
        }
        for (int base = st; base < en; base += 32) {
            int cnt = min(32, en - base);
            int id = (lane < cnt) ? __ldg(&g_csr_src[base + lane]) : 0;
            int j = 0;
            for (; j + 4 <= cnt; j += 4) {
                int i0 = __shfl_sync(0xffffffffu, id, j + half);
                int i1 = __shfl_sync(0xffffffffu, id, j + 2 + half);
                uint4 r0 = __ldg((const uint4*)(g_yh + (size_t)i0 * HID + hl * 8));
                uint4 r1 = __ldg((const uint4*)(g_yh + (size_t)i1 * HID + hl * 8));
                a0 = __hadd2(a0, __hadd2(*(__half2*)&r0.x, *(__half2*)&r1.x));
                a1 = __hadd2(a1, __hadd2(*(__half2*)&r0.y, *(__half2*)&r1.y));
                a2 = __hadd2(a2, __hadd2(*(__half2*)&r0.z, *(__half2*)&r1.z));
                a3 = __hadd2(a3, __hadd2(*(__half2*)&r0.w, *(__half2*)&r1.w));
            }
            if (j + 2 <= cnt) {
                int i0 = __shfl_sync(0xffffffffu, id, j + half);
                uint4 r0 = __ldg((const uint4*)(g_yh + (size_t)i0 * HID + hl * 8));
                a0 = __hadd2(a0, *(__half2*)&r0.x);
                a1 = __hadd2(a1, *(__half2*)&r0.y);
                a2 = __hadd2(a2, *(__half2*)&r0.z);
                a3 = __hadd2(a3, *(__half2*)&r0.w);
                j += 2;
            }
            if (j < cnt) {   // single leftover: half 0 adds, half 1 idles
                int i0 = __shfl_sync(0xffffffffu, id, j);
                uint4 r0 = __ldg((const uint4*)(g_yh + (size_t)i0 * HID + hl * 8));
                if (half == 0) {
                    a0 = __hadd2(a0, *(__half2*)&r0.x);
                    a1 = __hadd2(a1, *(__half2*)&r0.y);
                    a2 = __hadd2(a2, *(__half2*)&r0.z);
                    a3 = __hadd2(a3, *(__half2*)&r0.w);
                }
            }
        }
        // combine the two halves
        a0 = __hadd2(a0, h2_xor16(a0));
        a1 = __hadd2(a1, h2_xor16(a1));
        a2 = __hadd2(a2, h2_xor16(a2));
        a3 = __hadd2(a3, h2_xor16(a3));
        float2 f0 = __half22float2(a0);
        float2 f1 = __half22float2(a1);
        float2 f2 = __half22float2(a2);
        float2 f3 = __half22float2(a3);
        runA.x += fmaxf(fmaf(f0.x, dvn, bbA.x), 0.f);
        runA.y += fmaxf(fmaf(f0.y, dvn, bbA.y), 0.f);
        runA.z += fmaxf(fmaf(f1.x, dvn, bbA.z), 0.f);
        runA.w += fmaxf(fmaf(f1.y, dvn, bbA.w), 0.f);
        runB.x += fmaxf(fmaf(f2.x, dvn, bbB.x), 0.f);
        runB.y += fmaxf(fmaf(f2.y, dvn, bbB.y), 0.f);
        runB.z += fmaxf(fmaf(f3.x, dvn, bbB.z), 0.f);
        runB.w += fmaxf(fmaf(f3.y, dvn, bbB.w), 0.f);
        crun += 1.f;
    }
    if (lane < 16) {
        float* dA = g_gsum + curg * HID + hl * 8;
        asm volatile("red.global.add.v4.f32 [%0], {%1,%2,%3,%4};"
                     :: "l"(dA), "f"(runA.x), "f"(runA.y), "f"(runA.z), "f"(runA.w) : "memory");
        asm volatile("red.global.add.v4.f32 [%0], {%1,%2,%3,%4};"
                     :: "l"(dA + 4), "f"(runB.x), "f"(runB.y), "f"(runB.z), "f"(runB.w) : "memory");
    }
    if (lane == 0) atomicAdd(&g_gcnt[curg], crun);
}

// ---------------- input-side LSTM gates ----------------
__global__ __launch_bounds__(512) void k_gatesx(const float* __restrict__ w_ih,
                                                const float* __restrict__ b_ih,
                                                const float* __restrict__ b_hh) {
    __shared__ float p[HID];
    int t = blockIdx.x;
    if (threadIdx.x < HID) {
        float c = fmaxf(g_gcnt[t], 1.f);
        p[threadIdx.x] = g_gsum[t * HID + threadIdx.x] / c;
    }
    __syncthreads();
    int gg = threadIdx.x;
    const float4* wr = (const float4*)(w_ih + (size_t)gg * HID);
    float acc = __ldg(&b_ih[gg]) + __ldg(&b_hh[gg]);
#pragma unroll
    for (int j = 0; j < 32; j++) {
        float4 w = __ldg(wr + j);
        acc += w.x * p[j * 4] + w.y * p[j * 4 + 1] + w.z * p[j * 4 + 2] + w.w * p[j * 4 + 3];
    }
    g_gatesX[t * 512 + gg] = acc;
}

// ---------------- recurrent LSTM (fp16 weights, 4-way acc) + fused FC ----------------
__global__ __launch_bounds__(512) void k_lstm(const float* __restrict__ W_fc,
                                              const float* __restrict__ b_fc,
                                              float* __restrict__ out) {
    __shared__ float sh[HID];
    __shared__ float sg[4 * HID];
    int tid = threadIdx.x;
    float c = 0.f;
    if (tid < HID) sh[tid] = 0.f;
    __syncthreads();
    const uint4* wr = (const uint4*)(g_whh_h + (size_t)tid * HID);
    for (int t = 0; t < NGRAPH; t++) {
        float a0 = g_gatesX[t * 512 + tid], a1 = 0.f, a2 = 0.f, a3 = 0.f;
#pragma unroll
        for (int j = 0; j < 16; j += 4) {
#pragma unroll
            for (int u = 0; u < 4; u++) {
                uint4 w = __ldg(&wr[j + u]);
                float2 p0 = __half22float2(*(const __half2*)&w.x);
                float2 p1 = __half22float2(*(const __half2*)&w.y);
                float2 p2 = __half22float2(*(const __half2*)&w.z);
                float2 p3 = __half22float2(*(const __half2*)&w.w);
                const float* h = &sh[(j + u) * 8];
                a0 = fmaf(p0.x, h[0], a0); a1 = fmaf(p0.y, h[1], a1);
                a2 = fmaf(p1.x, h[2], a2); a3 = fmaf(p1.y, h[3], a3);
                a0 = fmaf(p2.x, h[4], a0); a1 = fmaf(p2.y, h[5], a1);
                a2 = fmaf(p3.x, h[6], a2); a3 = fmaf(p3.y, h[7], a3);
            }
        }
        sg[tid] = (a0 + a1) + (a2 + a3);
        __syncthreads();
        if (tid < HID) {
            float iv = 1.f / (1.f + __expf(-sg[tid]));
            float fv = 1.f / (1.f + __expf(-sg[HID + tid]));
            float gv = tanhf(sg[2 * HID + tid]);
            float ov = 1.f / (1.f + __expf(-sg[3 * HID + tid]));
            c = fv * c + iv * gv;
            sh[tid] = ov * tanhf(c);
        }
        __syncthreads();
        if (tid < 320) {
            int k = tid >> 5, lane = tid & 31;
            const float4* wf = (const float4*)(W_fc + (size_t)k * HID);
            float4 w = __ldg(&wf[lane]);
            float4 h4 = *(const float4*)&sh[lane * 4];
            float p = w.x * h4.x + w.y * h4.y + w.z * h4.z + w.w * h4.w;
            for (int o = 16; o > 0; o >>= 1) p += __shfl_down_sync(0xffffffffu, p, o);
            if (lane == 0) out[t * 10 + k] = p + __ldg(&b_fc[k]);
        }
    }
}

// ---------------- launch ----------------
extern "C" void kernel_launch(void* const* d_in, const int* in_sizes, int n_in,
                              void* d_out, int out_size) {
    const float* x      = (const float*)d_in[0];
    const int*   ei     = (const int*)d_in[1];
    const int*   batch  = (const int*)d_in[2];
    const float* W_gcn  = (const float*)d_in[3];
    const float* b_gcn  = (const float*)d_in[4];
    const float* w_ih   = (const float*)d_in[5];
    const float* w_hh   = (const float*)d_in[6];
    const float* b_ih   = (const float*)d_in[7];
    const float* b_hh   = (const float*)d_in[8];
    const float* W_fc   = (const float*)d_in[9];
    const float* b_fc   = (const float*)d_in[10];
    float* out = (float*)d_out;

    int N = in_sizes[2];       // 100000 nodes
    int E = in_sizes[1] / 2;   // 1600000 edges
    int NB = (N + SCAN_BLK - 1) / SCAN_BLK;

    static cudaStream_t s2 = nullptr;
    static cudaEvent_t ev0 = nullptr, evS1 = nullptr, evB = nullptr;
    if (s2 == nullptr) {
        cudaStreamCreate(&s2);
        cudaEventCreateWithFlags(&ev0, cudaEventDisableTiming);
        cudaEventCreateWithFlags(&evS1, cudaEventDisableTiming);
        cudaEventCreateWithFlags(&evB, cudaEventDisableTiming);
    }

    cudaEventRecord(ev0, 0);
    cudaStreamWaitEvent(s2, ev0, 0);   // s2 forks at t=0

    // main stream: degree -> scan -> CSR fill (submitted first; 4th launch = k_scan23 for ncu)
    k_init<<<(N + 255) / 256, 256>>>(N);
    k_deg<<<(E + 255) / 256, 256>>>(ei, E);
    k_scan1<<<NB, SCAN_BLK>>>(N);
    cudaEventRecord(evS1, 0);          // dinv ready
    k_scan23<<<NB, SCAN_BLK>>>(N, NB);
    k_fill<<<(E + 255) / 256, 256>>>(ei, E);

    // side stream: conversions + GEMM (independent), then yscale (needs dinv)
    k_cvtx<<<(N * HID / 8 + 255) / 256, 256, 0, s2>>>(x, N * HID / 8);
    k_cvtw<<<(4 * HID * HID + 255) / 256, 256, 0, s2>>>(W_gcn, w_hh);
    k_gemm_tc<<<(N + 127) / 128, 256, 0, s2>>>(N);
    cudaStreamWaitEvent(s2, evS1, 0);
    k_yscale<<<(N * 16 + 255) / 256, 256, 0, s2>>>(N * 16);
    cudaEventRecord(evB, s2);

    // join: agg needs CSR (main) + scaled y (s2)
    cudaStreamWaitEvent(0, evB, 0);
    k_agg<<<(N + 31) / 32, 256>>>(batch, b_gcn, N);
    k_gatesx<<<NGRAPH, 512>>>(w_ih, b_ih, b_hh);
    k_lstm<<<1, 512>>>(W_fc, b_fc, out);
}

// round 12
// speedup vs baseline: 1.0160x; 1.0160x over previous
#include <cuda_runtime.h>
#include <cuda_fp16.h>
#include <math.h>

#define NMAX 100000
#define EMAX 1600000
#define HID 128
#define NGRAPH 64
#define SCAN_BLK 512

// ---------------- device scratch ----------------
__device__ __half g_xh[(size_t)NMAX * HID];
__device__ __half g_wt[HID * HID];
__device__ __half g_yh[(size_t)NMAX * HID];    // fp16 xt, scaled by dinv in k_yscale
__device__ float g_dinv[NMAX];
__device__ int   g_deg[NMAX];                  // zeroed by k_gatesx of PREVIOUS run (.bss on first)
__device__ int   g_start[NMAX + 1];
__device__ int   g_cursor[NMAX];
__device__ int   g_csr_src[EMAX];
__device__ int   g_part[(NMAX + SCAN_BLK - 1) / SCAN_BLK];
__device__ float g_gsum[NGRAPH * HID];         // zeroed by k_gatesx after read
__device__ float g_gcnt[NGRAPH];
__device__ float g_gatesX[NGRAPH * 4 * HID];
__device__ __half g_whh_h[4 * HID * HID];

// ---------------- fp16 conversions ----------------
__global__ void k_cvtx(const float* __restrict__ x, int total8) {
    int i = blockIdx.x * blockDim.x + threadIdx.x;
    if (i < total8) {
        float4 v0 = __ldg((const float4*)x + (size_t)i * 2);
        float4 v1 = __ldg((const float4*)x + (size_t)i * 2 + 1);
        __half2 h0 = __floats2half2_rn(v0.x, v0.y);
        __half2 h1 = __floats2half2_rn(v0.z, v0.w);
        __half2 h2 = __floats2half2_rn(v1.x, v1.y);
        __half2 h3 = __floats2half2_rn(v1.z, v1.w);
        uint4 p;
        p.x = *(unsigned*)&h0; p.y = *(unsigned*)&h1;
        p.z = *(unsigned*)&h2; p.w = *(unsigned*)&h3;
        *(uint4*)(g_xh + (size_t)i * 8) = p;
    }
}

__global__ void k_cvtw(const float* __restrict__ W, const float* __restrict__ w_hh) {
    int i = blockIdx.x * blockDim.x + threadIdx.x;
    if (i < HID * HID) {
        int n = i >> 7, k = i & 127;
        g_wt[n * HID + k] = __float2half(__ldg(&W[k * HID + n]));
    }
    if (i < 4 * HID * HID) g_whh_h[i] = __float2half(__ldg(&w_hh[i]));
}

// ---------------- degree histogram over col ----------------
__global__ void k_deg(const int* __restrict__ ei, int E) {
    int e = blockIdx.x * blockDim.x + threadIdx.x;
    if (e < E) atomicAdd(&g_deg[__ldg(&ei[(size_t)E + e])], 1);
}

// ---------------- scan pass 1: block sums + dinv ----------------
__global__ __launch_bounds__(SCAN_BLK) void k_scan1(int N) {
    int i = blockIdx.x * SCAN_BLK + threadIdx.x;
    int v = (i < N) ? g_deg[i] : 0;
    if (i < N) g_dinv[i] = rsqrtf((float)v + 1.0f);
    int s = v;
    for (int o = 16; o > 0; o >>= 1) s += __shfl_down_sync(0xffffffffu, s, o);
    __shared__ int ws[16];
    int wid = threadIdx.x >> 5, lane = threadIdx.x & 31;
    if (lane == 0) ws[wid] = s;
    __syncthreads();
    if (threadIdx.x < 16) {
        int t = ws[threadIdx.x];
        for (int o = 8; o > 0; o >>= 1) t += __shfl_down_sync(0xffffu, t, o);
        if (threadIdx.x == 0) g_part[blockIdx.x] = t;
    }
}

// ---------------- scan 2+3 merged ----------------
__global__ __launch_bounds__(SCAN_BLK) void k_scan23(int N, int NB) {
    int bid = blockIdx.x;
    int i = bid * SCAN_BLK + threadIdx.x;
    int v = (i < N) ? g_deg[i] : 0;
    int lane = threadIdx.x & 31, wid = threadIdx.x >> 5;
    int x = v;
    for (int o = 1; o < 32; o <<= 1) {
        int t = __shfl_up_sync(0xffffffffu, x, o);
        if (lane >= o) x += t;
    }
    __shared__ int ws[16], pws[16], sbase;
    if (lane == 31) ws[wid] = x;
    int pv = ((int)threadIdx.x < bid) ? g_part[threadIdx.x] : 0;
    for (int o = 16; o > 0; o >>= 1) pv += __shfl_down_sync(0xffffffffu, pv, o);
    if (lane == 0) pws[wid] = pv;
    __syncthreads();
    if (wid == 0 && lane < 16) {
        int t = ws[lane];
        for (int o = 1; o < 16; o <<= 1) {
            int u = __shfl_up_sync(0xffffu, t, o);
            if (lane >= o) t += u;
        }
        ws[lane] = t;
    }
    if (wid == 1 && lane < 16) {
        int t = pws[lane];
        for (int o = 8; o > 0; o >>= 1) t += __shfl_down_sync(0xffffu, t, o);
        if (lane == 0) sbase = t;
    }
    __syncthreads();
    int base = sbase + (wid > 0 ? ws[wid - 1] : 0);
    int excl = base + (x - v);
    if (i < N) { g_start[i] = excl; g_cursor[i] = excl; }
    if (i == N - 1) g_start[N] = excl + v;
}

// ---------------- CSR fill: 4 edges/thread, int4 loads (4th submitted -> ncu slot) ----------------
__global__ void k_fill(const int* __restrict__ ei, int E) {
    int q = blockIdx.x * blockDim.x + threadIdx.x;
    if (q * 4 < E) {
        int4 rows = __ldg((const int4*)(ei) + q);
        int4 cols = __ldg((const int4*)(ei + E) + q);
        int s0 = atomicAdd(&g_cursor[cols.x], 1); g_csr_src[s0] = rows.x;
        int s1 = atomicAdd(&g_cursor[cols.y], 1); g_csr_src[s1] = rows.y;
        int s2 = atomicAdd(&g_cursor[cols.z], 1); g_csr_src[s2] = rows.z;
        int s3 = atomicAdd(&g_cursor[cols.w], 1); g_csr_src[s3] = rows.w;
    }
}

// ---------------- tensor-core GEMM: yh[n] = fp16( x[n] @ W ) ----------------
__global__ __launch_bounds__(256) void k_gemm_tc(int M) {
    __shared__ __half xs[128][72];
    __shared__ __half ws[128][72];
    int tid = threadIdx.x;
    int warp = tid >> 5, lane = tid & 31;
    int wm = (warp & 3) * 32;
    int wn = (warp >> 2) * 64;
    int g = lane >> 2, tig = lane & 3;
    int m0 = blockIdx.x * 128;

    float acc[2][8][4];
#pragma unroll
    for (int mt = 0; mt < 2; mt++)
#pragma unroll
        for (int nt = 0; nt < 8; nt++)
#pragma unroll
            for (int q = 0; q < 4; q++) acc[mt][nt][q] = 0.f;

    for (int kc = 0; kc < 2; kc++) {
#pragma unroll
        for (int i = 0; i < 4; i++) {
            int idx = i * 256 + tid;
            int r = idx >> 3, q = idx & 7;
            int grow = m0 + r;
            uint4 v = make_uint4(0u, 0u, 0u, 0u);
            if (grow < M)
                v = *(const uint4*)(g_xh + (size_t)grow * HID + kc * 64 + q * 8);
            *(uint4*)(&xs[r][q * 8]) = v;
            uint4 w = *(const uint4*)(g_wt + r * HID + kc * 64 + q * 8);
            *(uint4*)(&ws[r][q * 8]) = w;
        }
        __syncthreads();
#pragma unroll
        for (int ks = 0; ks < 4; ks++) {
            int k0 = ks * 16;
            unsigned a[2][4];
#pragma unroll
            for (int mt = 0; mt < 2; mt++) {
                int row = wm + mt * 16 + g;
                a[mt][0] = *(const unsigned*)(&xs[row][k0 + tig * 2]);
                a[mt][1] = *(const unsigned*)(&xs[row + 8][k0 + tig * 2]);
                a[mt][2] = *(const unsigned*)(&xs[row][k0 + tig * 2 + 8]);
                a[mt][3] = *(const unsigned*)(&xs[row + 8][k0 + tig * 2 + 8]);
            }
#pragma unroll
            for (int nt = 0; nt < 8; nt++) {
                int n = wn + nt * 8 + g;
                unsigned b0 = *(const unsigned*)(&ws[n][k0 + tig * 2]);
                unsigned b1 = *(const unsigned*)(&ws[n][k0 + tig * 2 + 8]);
#pragma unroll
                for (int mt = 0; mt < 2; mt++) {
                    float* c = acc[mt][nt];
                    asm volatile(
                        "mma.sync.aligned.m16n8k16.row.col.f32.f16.f16.f32 "
                        "{%0,%1,%2,%3}, {%4,%5,%6,%7}, {%8,%9}, {%0,%1,%2,%3};"
                        : "+f"(c[0]), "+f"(c[1]), "+f"(c[2]), "+f"(c[3])
                        : "r"(a[mt][0]), "r"(a[mt][1]), "r"(a[mt][2]), "r"(a[mt][3]),
                          "r"(b0), "r"(b1));
                }
            }
        }
        __syncthreads();
    }

#pragma unroll
    for (int mt = 0; mt < 2; mt++) {
        int row = m0 + wm + mt * 16 + g;
#pragma unroll
        for (int nt = 0; nt < 8; nt++) {
            int col = wn + nt * 8 + tig * 2;
            float* c = acc[mt][nt];
            if (row < M) {
                __half2 h = __floats2half2_rn(c[0], c[1]);
                *(__half2*)(g_yh + (size_t)row * HID + col) = h;
            }
            if (row + 8 < M) {
                __half2 h = __floats2half2_rn(c[2], c[3]);
                *(__half2*)(g_yh + (size_t)(row + 8) * HID + col) = h;
            }
        }
    }
}

// ---------------- yscale: g_yh[n] *= dinv[n] ----------------
__global__ void k_yscale(int total16) {
    int i = blockIdx.x * blockDim.x + threadIdx.x;
    if (i < total16) {
        int n = i >> 4;
        uint4 v = *(const uint4*)(g_yh + (size_t)i * 8);
        __half2 dh = __float2half2_rn(g_dinv[n]);
        __half2* p = (__half2*)&v;
        p[0] = __hmul2(p[0], dh);
        p[1] = __hmul2(p[1], dh);
        p[2] = __hmul2(p[2], dh);
        p[3] = __hmul2(p[3], dh);
        *(uint4*)(g_yh + (size_t)i * 8) = v;
    }
}

// ---------------- fused gather-aggregate + relu + mean-pool ----------------
__device__ __forceinline__ void pool_flush(int g, float4 run, float crun, int lane) {
    float* dst = g_gsum + g * HID + lane * 4;
    asm volatile("red.global.add.v4.f32 [%0], {%1,%2,%3,%4};"
                 :: "l"(dst), "f"(run.x), "f"(run.y), "f"(run.z), "f"(run.w) : "memory");
    if (lane == 0) atomicAdd(&g_gcnt[g], crun);
}

__device__ __forceinline__ void add_row(float4& acc, uint2 r) {
    float2 lo = __half22float2(*(const __half2*)&r.x);
    float2 hi = __half22float2(*(const __half2*)&r.y);
    acc.x += lo.x; acc.y += lo.y; acc.z += hi.x; acc.w += hi.y;
}

__global__ __launch_bounds__(256) void k_agg(const int* __restrict__ batch,
                                             const float* __restrict__ b_gcn, int N) {
    int lane = threadIdx.x & 31, wid = threadIdx.x >> 5;
    int s0 = blockIdx.x * 32;
    int e0 = min(s0 + 32, N);
    int n0 = s0 + wid;
    if (n0 >= e0) return;

    float4 bb = __ldg((const float4*)(b_gcn + lane * 4));
    int curg = __ldg(&batch[n0]);
    float4 run = make_float4(0.f, 0.f, 0.f, 0.f);
    float crun = 0.f;

    for (int n = n0; n < e0; n += 8) {
        int gg = __ldg(&batch[n]);
        if (gg != curg) {
            pool_flush(curg, run, crun, lane);
            run = make_float4(0.f, 0.f, 0.f, 0.f);
            crun = 0.f;
            curg = gg;
        }
        int st = __ldg(&g_start[n]);
        int en = __ldg(&g_start[n + 1]);
        float dvn = __ldg(&g_dinv[n]);
        float4 acc = make_float4(0.f, 0.f, 0.f, 0.f);
        add_row(acc, __ldg((const uint2*)(g_yh + (size_t)n * HID) + lane));  // self loop
        for (int base = st; base < en; base += 32) {
            int cnt = min(32, en - base);
            int id = (lane < cnt) ? __ldg(&g_csr_src[base + lane]) : 0;
            int j = 0;
            for (; j + 4 <= cnt; j += 4) {
                int a0 = __shfl_sync(0xffffffffu, id, j);
                int a1 = __shfl_sync(0xffffffffu, id, j + 1);
                int a2 = __shfl_sync(0xffffffffu, id, j + 2);
                int a3 = __shfl_sync(0xffffffffu, id, j + 3);
                uint2 r0 = __ldg((const uint2*)(g_yh + (size_t)a0 * HID) + lane);
                uint2 r1 = __ldg((const uint2*)(g_yh + (size_t)a1 * HID) + lane);
                uint2 r2 = __ldg((const uint2*)(g_yh + (size_t)a2 * HID) + lane);
                uint2 r3 = __ldg((const uint2*)(g_yh + (size_t)a3 * HID) + lane);
                add_row(acc, r0);
                add_row(acc, r1);
                add_row(acc, r2);
                add_row(acc, r3);
            }
            for (; j < cnt; j++) {
                int a0 = __shfl_sync(0xffffffffu, id, j);
                add_row(acc, __ldg((const uint2*)(g_yh + (size_t)a0 * HID) + lane));
            }
        }
        run.x += fmaxf(fmaf(acc.x, dvn, bb.x), 0.f);
        run.y += fmaxf(fmaf(acc.y, dvn, bb.y), 0.f);
        run.z += fmaxf(fmaf(acc.z, dvn, bb.z), 0.f);
        run.w += fmaxf(fmaf(acc.w, dvn, bb.w), 0.f);
        crun += 1.f;
    }
    pool_flush(curg, run, crun, lane);
}

// ---------------- input-side LSTM gates + state re-zero for next replay ----------------
__global__ __launch_bounds__(512) void k_gatesx(const float* __restrict__ w_ih,
                                                const float* __restrict__ b_ih,
                                                const float* __restrict__ b_hh, int N) {
    __shared__ float p[HID];
    int t = blockIdx.x;
    if (threadIdx.x < HID) {
        float c = fmaxf(g_gcnt[t], 1.f);
        p[threadIdx.x] = g_gsum[t * HID + threadIdx.x] / c;
    }
    __syncthreads();
    int gg = threadIdx.x;
    const float4* wr = (const float4*)(w_ih + (size_t)gg * HID);
    float acc = __ldg(&b_ih[gg]) + __ldg(&b_hh[gg]);
#pragma unroll
    for (int j = 0; j < 32; j++) {
        float4 w = __ldg(wr + j);
        acc += w.x * p[j * 4] + w.y * p[j * 4 + 1] + w.z * p[j * 4 + 2] + w.w * p[j * 4 + 3];
    }
    g_gatesX[t * 512 + gg] = acc;
    // re-zero accumulators for the NEXT kernel_launch invocation (post-read)
    if (threadIdx.x < HID) g_gsum[t * HID + threadIdx.x] = 0.f;
    if (threadIdx.x == 0) g_gcnt[t] = 0.f;
    for (int i = t * 512 + threadIdx.x; i < N; i += NGRAPH * 512) g_deg[i] = 0;
}

// ---------------- recurrent LSTM (fp16 weights, 4-way acc) + fused FC ----------------
__global__ __launch_bounds__(512) void k_lstm(const float* __restrict__ W_fc,
                                              const float* __restrict__ b_fc,
                                              float* __restrict__ out) {
    __shared__ float sh[HID];
    __shared__ float sg[4 * HID];
    int tid = threadIdx.x;
    float c = 0.f;
    if (tid < HID) sh[tid] = 0.f;
    __syncthreads();
    const uint4* wr = (const uint4*)(g_whh_h + (size_t)tid * HID);
    for (int t = 0; t < NGRAPH; t++) {
        float a0 = g_gatesX[t * 512 + tid], a1 = 0.f, a2 = 0.f, a3 = 0.f;
#pragma unroll
        for (int j = 0; j < 16; j += 4) {
#pragma unroll
            for (int u = 0; u < 4; u++) {
                uint4 w = __ldg(&wr[j + u]);
                float2 p0 = __half22float2(*(const __half2*)&w.x);
                float2 p1 = __half22float2(*(const __half2*)&w.y);
                float2 p2 = __half22float2(*(const __half2*)&w.z);
                float2 p3 = __half22float2(*(const __half2*)&w.w);
                const float* h = &sh[(j + u) * 8];
                a0 = fmaf(p0.x, h[0], a0); a1 = fmaf(p0.y, h[1], a1);
                a2 = fmaf(p1.x, h[2], a2); a3 = fmaf(p1.y, h[3], a3);
                a0 = fmaf(p2.x, h[4], a0); a1 = fmaf(p2.y, h[5], a1);
                a2 = fmaf(p3.x, h[6], a2); a3 = fmaf(p3.y, h[7], a3);
            }
        }
        sg[tid] = (a0 + a1) + (a2 + a3);
        __syncthreads();
        if (tid < HID) {
            float iv = 1.f / (1.f + __expf(-sg[tid]));
            float fv = 1.f / (1.f + __expf(-sg[HID + tid]));
            float gv = tanhf(sg[2 * HID + tid]);
            float ov = 1.f / (1.f + __expf(-sg[3 * HID + tid]));
            c = fv * c + iv * gv;
            sh[tid] = ov * tanhf(c);
        }
        __syncthreads();
        if (tid < 320) {
            int k = tid >> 5, lane = tid & 31;
            const float4* wf = (const float4*)(W_fc + (size_t)k * HID);
            float4 w = __ldg(&wf[lane]);
            float4 h4 = *(const float4*)&sh[lane * 4];
            float p = w.x * h4.x + w.y * h4.y + w.z * h4.z + w.w * h4.w;
            for (int o = 16; o > 0; o >>= 1) p += __shfl_down_sync(0xffffffffu, p, o);
            if (lane == 0) out[t * 10 + k] = p + __ldg(&b_fc[k]);
        }
    }
}

// ---------------- launch ----------------
extern "C" void kernel_launch(void* const* d_in, const int* in_sizes, int n_in,
                              void* d_out, int out_size) {
    const float* x      = (const float*)d_in[0];
    const int*   ei     = (const int*)d_in[1];
    const int*   batch  = (const int*)d_in[2];
    const float* W_gcn  = (const float*)d_in[3];
    const float* b_gcn  = (const float*)d_in[4];
    const float* w_ih   = (const float*)d_in[5];
    const float* w_hh   = (const float*)d_in[6];
    const float* b_ih   = (const float*)d_in[7];
    const float* b_hh   = (const float*)d_in[8];
    const float* W_fc   = (const float*)d_in[9];
    const float* b_fc   = (const float*)d_in[10];
    float* out = (float*)d_out;

    int N = in_sizes[2];       // 100000 nodes
    int E = in_sizes[1] / 2;   // 1600000 edges
    int NB = (N + SCAN_BLK - 1) / SCAN_BLK;

    static cudaStream_t s2 = nullptr;
    static cudaEvent_t ev0 = nullptr, evS1 = nullptr, evB = nullptr;
    if (s2 == nullptr) {
        cudaStreamCreate(&s2);
        cudaEventCreateWithFlags(&ev0, cudaEventDisableTiming);
        cudaEventCreateWithFlags(&evS1, cudaEventDisableTiming);
        cudaEventCreateWithFlags(&evB, cudaEventDisableTiming);
    }

    cudaEventRecord(ev0, 0);
    cudaStreamWaitEvent(s2, ev0, 0);

    // main stream (submitted first): deg(1) scan1(2) scan23(3) fill(4 <- ncu slot)
    k_deg<<<(E + 255) / 256, 256>>>(ei, E);
    k_scan1<<<NB, SCAN_BLK>>>(N);
    cudaEventRecord(evS1, 0);
    k_scan23<<<NB, SCAN_BLK>>>(N, NB);
    k_fill<<<(E / 4 + 255) / 256, 256>>>(ei, E);

    // side stream: conversions + GEMM, then yscale (needs dinv)
    k_cvtx<<<(N * HID / 8 + 255) / 256, 256, 0, s2>>>(x, N * HID / 8);
    k_cvtw<<<(4 * HID * HID + 255) / 256, 256, 0, s2>>>(W_gcn, w_hh);
    k_gemm_tc<<<(N + 127) / 128, 256, 0, s2>>>(N);
    cudaStreamWaitEvent(s2, evS1, 0);
    k_yscale<<<(N * 16 + 255) / 256, 256, 0, s2>>>(N * 16);
    cudaEventRecord(evB, s2);

    // join + agg + tail
    cudaStreamWaitEvent(0, evB, 0);
    k_agg<<<(N + 31) / 32, 256>>>(batch, b_gcn, N);
    k_gatesx<<<NGRAPH, 512>>>(w_ih, b_ih, b_hh, N);
    k_lstm<<<1, 512>>>(W_fc, b_fc, out);
}